// round 1
// baseline (speedup 1.0000x reference)
#include <cuda_runtime.h>
#include <cstdint>

// Problem constants
#define OUT_F      4096
#define IN_F       4096
#define KDIM       4096
#define MROWS      8192                       // 4 * 2048
#define NBLOCKS    (OUT_F * IN_F / 8)         // 2,097,152 codebook blocks

// GEMM tiling
#define BM 128
#define BN 128
#define BK 32
#define LDS_STRIDE 36                         // 32 + 4 pad: conflict-free, float4-aligned

// 67 MB reconstructed weight (tf32-rounded fp32 bits), device-global scratch
__device__ float g_W[(size_t)OUT_F * IN_F];
__device__ int   g_idx_is32;

// ---------------------------------------------------------------------------
// tf32 round-to-nearest (rna). Truncation would bias the dot products by
// ~1e-3 relative and blow the error budget; rna keeps it ~3e-4.
// ---------------------------------------------------------------------------
__device__ __forceinline__ float to_tf32(float x) {
    float y;
    asm("cvt.rna.tf32.f32 %0, %1;" : "=f"(y) : "f"(x));
    return y;
}

// ---------------------------------------------------------------------------
// Index dtype sniffer: jax demotes int64->int32 unless x64 is on. If the
// buffer really is int64 (LE), every odd 32-bit word among the first NBLOCKS
// words is a zero high-half. Random int32 indices make that ~impossible.
// ---------------------------------------------------------------------------
__global__ void k_init_flag() { g_idx_is32 = 0; }

__global__ void k_detect_idx32(const int* __restrict__ w) {
    int i = blockIdx.x * blockDim.x + threadIdx.x;
    int pos = 2 * i + 1;
    if (pos < NBLOCKS) {
        if (w[pos] != 0) g_idx_is32 = 1;   // racy same-value store: fine
    }
}

// ---------------------------------------------------------------------------
// Reconstruct W[out, in] from codebook[4096, 8] via indices, tf32-rounded.
// NBLOCKS*8 == OUT_F*IN_F exactly, so no tail slicing needed.
// ---------------------------------------------------------------------------
__global__ void k_reconstruct(const void* __restrict__ indices,
                              const float* __restrict__ cb) {
    long long b = (long long)blockIdx.x * blockDim.x + threadIdx.x;
    if (b >= NBLOCKS) return;
    long long v;
    if (g_idx_is32) v = ((const int*)indices)[b];
    else            v = ((const long long*)indices)[b];
    const float4* src = (const float4*)(cb + v * 8);
    float4 lo = src[0], hi = src[1];
    lo.x = to_tf32(lo.x); lo.y = to_tf32(lo.y);
    lo.z = to_tf32(lo.z); lo.w = to_tf32(lo.w);
    hi.x = to_tf32(hi.x); hi.y = to_tf32(hi.y);
    hi.z = to_tf32(hi.z); hi.w = to_tf32(hi.w);
    float4* dst = (float4*)(g_W + b * 8);
    dst[0] = lo;
    dst[1] = hi;
}

// ---------------------------------------------------------------------------
// TF32 mma.sync m16n8k8 (row.col): A row-major 16x8, B col-major 8x8.
// Both x[m,k] and W[n,k] are k-contiguous -> maps directly to row.col.
// ---------------------------------------------------------------------------
__device__ __forceinline__ void mma_tf32(float* c, const uint32_t* a, const uint32_t* b) {
    asm volatile(
        "mma.sync.aligned.m16n8k8.row.col.f32.tf32.tf32.f32 "
        "{%0,%1,%2,%3}, {%4,%5,%6,%7}, {%8,%9}, {%0,%1,%2,%3};"
        : "+f"(c[0]), "+f"(c[1]), "+f"(c[2]), "+f"(c[3])
        : "r"(a[0]), "r"(a[1]), "r"(a[2]), "r"(a[3]),
          "r"(b[0]), "r"(b[1]));
}

// ---------------------------------------------------------------------------
// GEMM: C[8192,4096] = x[8192,4096] * W[4096,4096]^T + bias
// 256 threads = 8 warps (4 in M, 2 in N); warp tile 32x64; BK=32 (4 k-steps).
// ---------------------------------------------------------------------------
__global__ __launch_bounds__(256, 1)
void k_gemm(const float* __restrict__ A,
            const float* __restrict__ bias,
            float* __restrict__ C) {
    __shared__ float As[BM * LDS_STRIDE];   // 18 KB
    __shared__ float Bs[BN * LDS_STRIDE];   // 18 KB

    const int tid  = threadIdx.x;
    const int lane = tid & 31;
    const int warp = tid >> 5;
    const int gid  = lane >> 2;     // group id 0..7
    const int tg   = lane & 3;      // thread-in-group 0..3
    const int wm   = warp & 3;      // warp M coord: 0..3  (32 rows each)
    const int wn   = warp >> 2;     // warp N coord: 0..1  (64 cols each)

    const int m0 = blockIdx.y * BM;
    const int n0 = blockIdx.x * BN;

    const float* Ablk = A   + (long long)m0 * KDIM;
    const float* Bblk = g_W + (long long)n0 * KDIM;

    float acc[2][8][4];
    #pragma unroll
    for (int i = 0; i < 2; i++)
        #pragma unroll
        for (int j = 0; j < 8; j++)
            #pragma unroll
            for (int r = 0; r < 4; r++) acc[i][j][r] = 0.f;

    for (int kt = 0; kt < KDIM; kt += BK) {
        // stage global -> regs (128x32 tile each for A and B; 4 float4/thread)
        float4 a_stage[4], b_stage[4];
        #pragma unroll
        for (int i = 0; i < 4; i++) {
            int v = tid + i * 256;
            int r = v >> 3;
            int c = (v & 7) * 4;
            a_stage[i] = *(const float4*)(Ablk + (long long)r * KDIM + kt + c);
            b_stage[i] = *(const float4*)(Bblk + (long long)r * KDIM + kt + c);
        }
        __syncthreads();   // previous tile fully consumed
        #pragma unroll
        for (int i = 0; i < 4; i++) {
            int v = tid + i * 256;
            int r = v >> 3;
            int c = (v & 7) * 4;
            float4 a = a_stage[i];
            a.x = to_tf32(a.x); a.y = to_tf32(a.y);
            a.z = to_tf32(a.z); a.w = to_tf32(a.w);
            *(float4*)(As + r * LDS_STRIDE + c) = a;          // W already tf32
            *(float4*)(Bs + r * LDS_STRIDE + c) = b_stage[i];
        }
        __syncthreads();

        #pragma unroll
        for (int ks = 0; ks < BK / 8; ks++) {
            uint32_t a_frag[2][4];
            uint32_t b_frag[8][2];
            #pragma unroll
            for (int mf = 0; mf < 2; mf++) {
                int r = wm * 32 + mf * 16 + gid;
                const float* p0 = As + r * LDS_STRIDE + ks * 8;
                const float* p1 = As + (r + 8) * LDS_STRIDE + ks * 8;
                a_frag[mf][0] = __float_as_uint(p0[tg]);
                a_frag[mf][1] = __float_as_uint(p1[tg]);
                a_frag[mf][2] = __float_as_uint(p0[tg + 4]);
                a_frag[mf][3] = __float_as_uint(p1[tg + 4]);
            }
            #pragma unroll
            for (int nf = 0; nf < 8; nf++) {
                int n = wn * 64 + nf * 8 + gid;
                const float* p = Bs + n * LDS_STRIDE + ks * 8;
                b_frag[nf][0] = __float_as_uint(p[tg]);
                b_frag[nf][1] = __float_as_uint(p[tg + 4]);
            }
            #pragma unroll
            for (int mf = 0; mf < 2; mf++)
                #pragma unroll
                for (int nf = 0; nf < 8; nf++)
                    mma_tf32(acc[mf][nf], a_frag[mf], b_frag[nf]);
        }
        __syncthreads();
    }

    // epilogue: bias add, direct fp32 stores (float2 per C fragment half)
    const int mbase = m0 + wm * 32;
    const int nbase = n0 + wn * 64;
    #pragma unroll
    for (int nf = 0; nf < 8; nf++) {
        int cc = nbase + nf * 8 + 2 * tg;
        float bv0 = bias[cc];
        float bv1 = bias[cc + 1];
        #pragma unroll
        for (int mf = 0; mf < 2; mf++) {
            int r = mbase + mf * 16 + gid;
            float2 v0 = make_float2(acc[mf][nf][0] + bv0, acc[mf][nf][1] + bv1);
            float2 v1 = make_float2(acc[mf][nf][2] + bv0, acc[mf][nf][3] + bv1);
            *(float2*)(C + (long long)r * OUT_F + cc)       = v0;
            *(float2*)(C + (long long)(r + 8) * OUT_F + cc) = v1;
        }
    }
}

// ---------------------------------------------------------------------------
extern "C" void kernel_launch(void* const* d_in, const int* in_sizes, int n_in,
                              void* d_out, int out_size) {
    const float* x    = (const float*)d_in[0];   // [4,2048,4096]
    const float* cb   = (const float*)d_in[1];   // [4096,8]
    const void*  idx  = d_in[2];                 // [NBLOCKS] int32 or int64
    const float* bias = (const float*)d_in[3];   // [4096]
    float* out = (float*)d_out;                  // [4,2048,4096]

    k_init_flag<<<1, 1>>>();
    {
        int nthreads = NBLOCKS / 2;
        k_detect_idx32<<<(nthreads + 255) / 256, 256>>>((const int*)idx);
    }
    k_reconstruct<<<(NBLOCKS + 255) / 256, 256>>>(idx, cb);

    dim3 grid(OUT_F / BN, MROWS / BM);   // (32, 64)
    k_gemm<<<grid, 256>>>(x, bias, out);
}

// round 3
// speedup vs baseline: 2.0921x; 2.0921x over previous
#include <cuda_runtime.h>
#include <cstdint>

// ---------------------------------------------------------------- constants
#define OUT_F   4096
#define IN_F    4096
#define KDIM    4096
#define MROWS   8192                      // 4 * 2048
#define NBLOCKS (OUT_F * IN_F / 8)        // 2,097,152

// GEMM tiling (mma.sync tf32, sm80-style async pipeline)
#define BM      128
#define BN      256
#define BK      32
#define NSTAGE  4
#define NITER   (KDIM / BK)               // 128
#define KSTEPS  (BK / 8)                  // 4 mma k-steps per stage

// SMEM stage layout: rows of exactly 128B (32 floats), XOR-swizzled 16B chunks
#define A_STAGE_BYTES (BM * 128)          // 16 KB
#define B_STAGE_BYTES (BN * 128)          // 32 KB
#define STAGE_BYTES   (A_STAGE_BYTES + B_STAGE_BYTES)      // 48 KB
#define SMEM_TOTAL    (NSTAGE * STAGE_BYTES)               // 192 KB

// scratch: tf32-rounded operands
__device__ float g_W[(size_t)OUT_F * IN_F];   // 67 MB
__device__ float g_X[(size_t)MROWS * KDIM];   // 134 MB
__device__ int   g_idx_is32;

// ---------------------------------------------------------------- helpers
__device__ __forceinline__ float to_tf32(float x) {
    float y;
    asm("cvt.rna.tf32.f32 %0, %1;" : "=f"(y) : "f"(x));
    return y;
}
__device__ __forceinline__ uint32_t smem_u32(const void* p) {
    uint32_t a;
    asm("{ .reg .u64 t; cvta.to.shared.u64 t, %1; cvt.u32.u64 %0, t; }"
        : "=r"(a) : "l"(p));
    return a;
}

#define CP_ASYNC16(sm, gp) \
    asm volatile("cp.async.cg.shared.global [%0], [%1], 16;" :: "r"(sm), "l"(gp) : "memory")
#define CP_COMMIT() asm volatile("cp.async.commit_group;" ::: "memory")
#define CP_WAIT(n)  asm volatile("cp.async.wait_group %0;" :: "n"(n) : "memory")

__device__ __forceinline__ void mma_tf32(float* c, const uint32_t* a, const uint32_t* b) {
    asm volatile(
        "mma.sync.aligned.m16n8k8.row.col.f32.tf32.tf32.f32 "
        "{%0,%1,%2,%3}, {%4,%5,%6,%7}, {%8,%9}, {%0,%1,%2,%3};"
        : "+f"(c[0]), "+f"(c[1]), "+f"(c[2]), "+f"(c[3])
        : "r"(a[0]), "r"(a[1]), "r"(a[2]), "r"(a[3]),
          "r"(b[0]), "r"(b[1]));
}

// ---------------------------------------------------------------- pre-passes
__global__ void k_init_flag() { g_idx_is32 = 0; }

__global__ void k_detect_idx32(const int* __restrict__ w) {
    int i = blockIdx.x * blockDim.x + threadIdx.x;
    int pos = 2 * i + 1;
    if (pos < NBLOCKS && w[pos] != 0) g_idx_is32 = 1;
}

__global__ void k_reconstruct(const void* __restrict__ indices,
                              const float* __restrict__ cb) {
    long long b = (long long)blockIdx.x * blockDim.x + threadIdx.x;
    if (b >= NBLOCKS) return;
    long long v;
    if (g_idx_is32) v = ((const int*)indices)[b];
    else            v = ((const long long*)indices)[b];
    const float4* src = (const float4*)(cb + v * 8);
    float4 lo = src[0], hi = src[1];
    lo.x = to_tf32(lo.x); lo.y = to_tf32(lo.y);
    lo.z = to_tf32(lo.z); lo.w = to_tf32(lo.w);
    hi.x = to_tf32(hi.x); hi.y = to_tf32(hi.y);
    hi.z = to_tf32(hi.z); hi.w = to_tf32(hi.w);
    float4* dst = (float4*)(g_W + b * 8);
    dst[0] = lo; dst[1] = hi;
}

__global__ void k_round_x(const float4* __restrict__ x) {
    size_t i = (size_t)blockIdx.x * blockDim.x + threadIdx.x;
    float4 v = x[i];
    v.x = to_tf32(v.x); v.y = to_tf32(v.y);
    v.z = to_tf32(v.z); v.w = to_tf32(v.w);
    ((float4*)g_X)[i] = v;
}

// ---------------------------------------------------------------- GEMM
// C[8192,4096] = X * W^T + bias.  CTA tile 128x256, 8 warps (2 M x 4 N),
// warp tile 64x64, BK=32, 4-stage cp.async pipeline, XOR-swizzled smem.
__global__ __launch_bounds__(256, 1)
void k_gemm(const float* __restrict__ bias, float* __restrict__ C) {
    extern __shared__ float smem[];
    const uint32_t smem_b = smem_u32(smem);

    const int tid  = threadIdx.x;
    const int lane = tid & 31;
    const int wid  = tid >> 5;
    const int gid  = lane >> 2;       // 0..7
    const int tg   = lane & 3;        // 0..3
    const int wm   = wid & 1;         // warp M: 0..1 (64 rows each)
    const int wn   = wid >> 1;        // warp N: 0..3 (64 cols each)

    const int m0 = blockIdx.y * BM;
    const int n0 = blockIdx.x * BN;

    // ---- cp.async addressing: A 4 chunks/thread, B 8 chunks/thread
    uint32_t sAoff[4], sBoff[8];
    const float* gA[4];
    const float* gB[8];
    #pragma unroll
    for (int i = 0; i < 4; i++) {
        int v = tid + i * 256, r = v >> 3, ch = v & 7;
        sAoff[i] = (uint32_t)(r * 128 + ((ch ^ (r & 7)) << 4));
        gA[i]    = g_X + (size_t)(m0 + r) * KDIM + ch * 4;
    }
    #pragma unroll
    for (int i = 0; i < 8; i++) {
        int v = tid + i * 256, r = v >> 3, ch = v & 7;
        sBoff[i] = (uint32_t)(r * 128 + ((ch ^ (r & 7)) << 4));
        gB[i]    = g_W + (size_t)(n0 + r) * KDIM + ch * 4;
    }

    // ---- prefill NSTAGE-1 stages
    #pragma unroll
    for (int s = 0; s < NSTAGE - 1; s++) {
        uint32_t ab = smem_b + s * STAGE_BYTES;
        uint32_t bb = ab + A_STAGE_BYTES;
        int kt = s * BK;
        #pragma unroll
        for (int i = 0; i < 4; i++) CP_ASYNC16(ab + sAoff[i], gA[i] + kt);
        #pragma unroll
        for (int i = 0; i < 8; i++) CP_ASYNC16(bb + sBoff[i], gB[i] + kt);
        CP_COMMIT();
    }

    float acc[4][8][4];
    #pragma unroll
    for (int mf = 0; mf < 4; mf++)
        #pragma unroll
        for (int nf = 0; nf < 8; nf++)
            #pragma unroll
            for (int r = 0; r < 4; r++) acc[mf][nf][r] = 0.f;

    // per-warp smem float bases (element units)
    const int aRowBase = (wm * 64 + gid);        // + mf*16 (+8)
    const int bRowBase = (wn * 64 + gid);        // + nf*8

    for (int it = 0; it < NITER; it++) {
        const int s = it & (NSTAGE - 1);
        CP_WAIT(2);
        __syncthreads();

        // refill the stage consumed in iteration it-1
        const int nf_it = it + NSTAGE - 1;
        if (nf_it < NITER) {
            const int fs = nf_it & (NSTAGE - 1);
            uint32_t ab = smem_b + fs * STAGE_BYTES;
            uint32_t bb = ab + A_STAGE_BYTES;
            const int kt = nf_it * BK;
            #pragma unroll
            for (int j = 0; j < 4; j++) CP_ASYNC16(ab + sAoff[j], gA[j] + kt);
            #pragma unroll
            for (int j = 0; j < 8; j++) CP_ASYNC16(bb + sBoff[j], gB[j] + kt);
        }
        CP_COMMIT();

        const float* As = smem + (s * STAGE_BYTES) / 4;
        const float* Bs = As + A_STAGE_BYTES / 4;

        #pragma unroll
        for (int ks = 0; ks < KSTEPS; ks++) {
            // swizzled chunk offsets for k = ks*8 + tg (+4)
            const int c0 = (((ks << 1)    ) ^ gid) << 2;
            const int c1 = (((ks << 1) | 1) ^ gid) << 2;

            uint32_t a_frag[4][4];
            #pragma unroll
            for (int mf = 0; mf < 4; mf++) {
                const float* p = As + (aRowBase + mf * 16) * 32 + tg;
                a_frag[mf][0] = __float_as_uint(p[c0]);
                a_frag[mf][1] = __float_as_uint(p[8 * 32 + c0]);
                a_frag[mf][2] = __float_as_uint(p[c1]);
                a_frag[mf][3] = __float_as_uint(p[8 * 32 + c1]);
            }
            uint32_t b_frag[8][2];
            #pragma unroll
            for (int nf = 0; nf < 8; nf++) {
                const float* q = Bs + (bRowBase + nf * 8) * 32 + tg;
                b_frag[nf][0] = __float_as_uint(q[c0]);
                b_frag[nf][1] = __float_as_uint(q[c1]);
            }
            #pragma unroll
            for (int mf = 0; mf < 4; mf++)
                #pragma unroll
                for (int nf = 0; nf < 8; nf++)
                    mma_tf32(acc[mf][nf], a_frag[mf], b_frag[nf]);
        }
    }

    // ---- epilogue: bias + store
    const int mbase = m0 + wm * 64;
    const int nbase = n0 + wn * 64;
    #pragma unroll
    for (int nf = 0; nf < 8; nf++) {
        const int cc = nbase + nf * 8 + 2 * tg;
        const float bv0 = __ldg(bias + cc);
        const float bv1 = __ldg(bias + cc + 1);
        #pragma unroll
        for (int mf = 0; mf < 4; mf++) {
            const int r = mbase + mf * 16 + gid;
            float2 v0 = make_float2(acc[mf][nf][0] + bv0, acc[mf][nf][1] + bv1);
            float2 v1 = make_float2(acc[mf][nf][2] + bv0, acc[mf][nf][3] + bv1);
            *(float2*)(C + (size_t)r * OUT_F + cc)       = v0;
            *(float2*)(C + (size_t)(r + 8) * OUT_F + cc) = v1;
        }
    }
}

// ---------------------------------------------------------------- launch
extern "C" void kernel_launch(void* const* d_in, const int* in_sizes, int n_in,
                              void* d_out, int out_size) {
    const float* x    = (const float*)d_in[0];   // [4,2048,4096]
    const float* cb   = (const float*)d_in[1];   // [4096,8]
    const void*  idx  = d_in[2];                 // [NBLOCKS] int32 or int64
    const float* bias = (const float*)d_in[3];   // [4096]
    float* out = (float*)d_out;

    k_init_flag<<<1, 1>>>();
    k_detect_idx32<<<(NBLOCKS / 2 + 255) / 256, 256>>>((const int*)idx);
    k_reconstruct<<<(NBLOCKS + 255) / 256, 256>>>(idx, cb);
    k_round_x<<<(int)((MROWS * (size_t)KDIM / 4 + 255) / 256), 256>>>((const float4*)x);

    cudaFuncSetAttribute(k_gemm, cudaFuncAttributeMaxDynamicSharedMemorySize, SMEM_TOTAL);
    dim3 grid(OUT_F / BN, MROWS / BM);   // (16, 64)
    k_gemm<<<grid, 256, SMEM_TOTAL>>>(bias, out);
}

// round 4
// speedup vs baseline: 3.9851x; 1.9048x over previous
#include <cuda_runtime.h>
#include <cuda_fp16.h>
#include <cstdint>

// ---------------------------------------------------------------- constants
#define OUT_F   4096
#define IN_F    4096
#define KDIM    4096
#define MROWS   8192
#define NBLOCKS (OUT_F * IN_F / 8)        // 2,097,152

// GEMM tiling (fp16 mma.sync m16n8k16, cp.async pipeline)
#define BM      128
#define BN      256
#define BK      64                        // 64 fp16 = 128B row
#define NSTAGE  4
#define NITER   (KDIM / BK)               // 64
#define KSTEPS  (BK / 16)                 // 4 k16 steps per stage

#define A_STAGE_BYTES (BM * 128)          // 16 KB
#define B_STAGE_BYTES (BN * 128)          // 32 KB
#define STAGE_BYTES   (A_STAGE_BYTES + B_STAGE_BYTES)   // 48 KB
#define SMEM_TOTAL    (NSTAGE * STAGE_BYTES)            // 192 KB

// scratch: fp16(rn)-rounded operands
__device__ __half g_Wh[(size_t)OUT_F * IN_F];   // 34 MB
__device__ __half g_Xh[(size_t)MROWS * KDIM];   // 67 MB
__device__ int    g_idx_is32;

// ---------------------------------------------------------------- helpers
__device__ __forceinline__ uint32_t smem_u32(const void* p) {
    uint32_t a;
    asm("{ .reg .u64 t; cvta.to.shared.u64 t, %1; cvt.u32.u64 %0, t; }"
        : "=r"(a) : "l"(p));
    return a;
}

#define CP_ASYNC16(sm, gp) \
    asm volatile("cp.async.cg.shared.global [%0], [%1], 16;" :: "r"(sm), "l"(gp) : "memory")
#define CP_COMMIT() asm volatile("cp.async.commit_group;" ::: "memory")
#define CP_WAIT(n)  asm volatile("cp.async.wait_group %0;" :: "n"(n) : "memory")

#define LDMATRIX_X4(r, a) \
    asm volatile("ldmatrix.sync.aligned.m8n8.x4.shared.b16 {%0,%1,%2,%3}, [%4];" \
                 : "=r"((r)[0]), "=r"((r)[1]), "=r"((r)[2]), "=r"((r)[3]) : "r"(a))
#define LDMATRIX_X2(r, a) \
    asm volatile("ldmatrix.sync.aligned.m8n8.x2.shared.b16 {%0,%1}, [%2];" \
                 : "=r"((r)[0]), "=r"((r)[1]) : "r"(a))

__device__ __forceinline__ void mma_f16(float* c, const uint32_t* a, const uint32_t* b) {
    asm volatile(
        "mma.sync.aligned.m16n8k16.row.col.f32.f16.f16.f32 "
        "{%0,%1,%2,%3}, {%4,%5,%6,%7}, {%8,%9}, {%0,%1,%2,%3};"
        : "+f"(c[0]), "+f"(c[1]), "+f"(c[2]), "+f"(c[3])
        : "r"(a[0]), "r"(a[1]), "r"(a[2]), "r"(a[3]),
          "r"(b[0]), "r"(b[1]));
}

// ---------------------------------------------------------------- pre-passes
__global__ void k_init_flag() { g_idx_is32 = 0; }

__global__ void k_detect_idx32(const int* __restrict__ w) {
    int i = blockIdx.x * blockDim.x + threadIdx.x;
    int pos = 2 * i + 1;
    if (pos < NBLOCKS && w[pos] != 0) g_idx_is32 = 1;
}

// gather codebook block -> 8 fp16 (rn) -> 16B store
__global__ void k_reconstruct(const void* __restrict__ indices,
                              const float* __restrict__ cb) {
    long long b = (long long)blockIdx.x * blockDim.x + threadIdx.x;
    if (b >= NBLOCKS) return;
    long long v;
    if (g_idx_is32) v = ((const int*)indices)[b];
    else            v = ((const long long*)indices)[b];
    const float4* src = (const float4*)(cb + v * 8);
    float4 lo = src[0], hi = src[1];
    __half2 h[4];
    h[0] = __floats2half2_rn(lo.x, lo.y);
    h[1] = __floats2half2_rn(lo.z, lo.w);
    h[2] = __floats2half2_rn(hi.x, hi.y);
    h[3] = __floats2half2_rn(hi.z, hi.w);
    *(uint4*)(g_Wh + b * 8) = *(uint4*)h;
}

// x fp32 -> fp16 (rn); 8 floats per thread
__global__ void k_to_half(const float4* __restrict__ x) {
    size_t i = (size_t)blockIdx.x * blockDim.x + threadIdx.x;
    float4 a = x[2 * i], b = x[2 * i + 1];
    __half2 h[4];
    h[0] = __floats2half2_rn(a.x, a.y);
    h[1] = __floats2half2_rn(a.z, a.w);
    h[2] = __floats2half2_rn(b.x, b.y);
    h[3] = __floats2half2_rn(b.z, b.w);
    *(uint4*)(g_Xh + i * 8) = *(uint4*)h;
}

// ---------------------------------------------------------------- GEMM
// C[8192,4096] = X * W^T + bias. CTA 128x256, 8 warps (2M x 4N), warp 64x64.
// fp16 m16n8k16, ldmatrix fragments, 4-stage cp.async, XOR-swizzled smem.
__global__ __launch_bounds__(256, 1)
void k_gemm(const float* __restrict__ bias, float* __restrict__ C) {
    extern __shared__ char smem[];
    const uint32_t smem_b = smem_u32(smem);

    const int tid  = threadIdx.x;
    const int lane = tid & 31;
    const int wid  = tid >> 5;
    const int gid  = lane >> 2;
    const int tg   = lane & 3;
    const int wm   = wid & 1;         // 0..1 (64 rows)
    const int wn   = wid >> 1;        // 0..3 (64 cols)

    const int m0 = blockIdx.y * BM;
    const int n0 = blockIdx.x * BN;

    // ---- cp.async addressing (A: 4 chunks/thread, B: 8; chunk = 16B = 8 fp16)
    uint32_t sAoff[4], sBoff[8];
    const __half* gA[4];
    const __half* gB[8];
    #pragma unroll
    for (int i = 0; i < 4; i++) {
        int v = tid + i * 256, r = v >> 3, ch = v & 7;
        sAoff[i] = (uint32_t)(r * 128 + ((ch ^ (r & 7)) << 4));
        gA[i]    = g_Xh + (size_t)(m0 + r) * KDIM + ch * 8;
    }
    #pragma unroll
    for (int i = 0; i < 8; i++) {
        int v = tid + i * 256, r = v >> 3, ch = v & 7;
        sBoff[i] = (uint32_t)(r * 128 + ((ch ^ (r & 7)) << 4));
        gB[i]    = g_Wh + (size_t)(n0 + r) * KDIM + ch * 8;
    }

    // ---- ldmatrix per-lane bases (byte offsets inside a stage)
    const int row_off = lane & 7;
    const int a_kb = lane >> 4;               // k+8 selector for A (x4)
    const int b_kb = (lane >> 3) & 1;         // k+8 selector for B (x2)
    uint32_t aoff[4], boff[8];
    #pragma unroll
    for (int mf = 0; mf < 4; mf++)
        aoff[mf] = (uint32_t)((wm * 64 + mf * 16 + row_off + ((lane >> 3) & 1) * 8) * 128);
    #pragma unroll
    for (int nf = 0; nf < 8; nf++)
        boff[nf] = (uint32_t)(A_STAGE_BYTES + (wn * 64 + nf * 8 + row_off) * 128);

    // ---- prefill
    #pragma unroll
    for (int s = 0; s < NSTAGE - 1; s++) {
        uint32_t ab = smem_b + s * STAGE_BYTES;
        uint32_t bb = ab + A_STAGE_BYTES;
        int kt = s * BK;
        #pragma unroll
        for (int i = 0; i < 4; i++) CP_ASYNC16(ab + sAoff[i], gA[i] + kt);
        #pragma unroll
        for (int i = 0; i < 8; i++) CP_ASYNC16(bb + sBoff[i], gB[i] + kt);
        CP_COMMIT();
    }

    float acc[4][8][4];
    #pragma unroll
    for (int mf = 0; mf < 4; mf++)
        #pragma unroll
        for (int nf = 0; nf < 8; nf++)
            #pragma unroll
            for (int r = 0; r < 4; r++) acc[mf][nf][r] = 0.f;

    for (int it = 0; it < NITER; it++) {
        const int s = it & (NSTAGE - 1);
        CP_WAIT(2);
        __syncthreads();

        const int nx = it + NSTAGE - 1;
        if (nx < NITER) {
            const int fs = nx & (NSTAGE - 1);
            uint32_t ab = smem_b + fs * STAGE_BYTES;
            uint32_t bb = ab + A_STAGE_BYTES;
            const int kt = nx * BK;
            #pragma unroll
            for (int j = 0; j < 4; j++) CP_ASYNC16(ab + sAoff[j], gA[j] + kt);
            #pragma unroll
            for (int j = 0; j < 8; j++) CP_ASYNC16(bb + sBoff[j], gB[j] + kt);
        }
        CP_COMMIT();

        const uint32_t stage = smem_b + s * STAGE_BYTES;

        #pragma unroll
        for (int ks = 0; ks < KSTEPS; ks++) {
            const uint32_t ac = (uint32_t)((((2 * ks) | a_kb) ^ row_off) << 4);
            const uint32_t bc = (uint32_t)((((2 * ks) | b_kb) ^ row_off) << 4);

            uint32_t a_frag[4][4], b_frag[8][2];
            #pragma unroll
            for (int mf = 0; mf < 4; mf++)
                LDMATRIX_X4(a_frag[mf], stage + aoff[mf] + ac);
            #pragma unroll
            for (int nf = 0; nf < 8; nf++)
                LDMATRIX_X2(b_frag[nf], stage + boff[nf] + bc);

            #pragma unroll
            for (int mf = 0; mf < 4; mf++)
                #pragma unroll
                for (int nf = 0; nf < 8; nf++)
                    mma_f16(acc[mf][nf], a_frag[mf], b_frag[nf]);
        }
    }

    // ---- epilogue: bias + store
    const int mbase = m0 + wm * 64;
    const int nbase = n0 + wn * 64;
    #pragma unroll
    for (int nf = 0; nf < 8; nf++) {
        const int cc = nbase + nf * 8 + 2 * tg;
        const float bv0 = __ldg(bias + cc);
        const float bv1 = __ldg(bias + cc + 1);
        #pragma unroll
        for (int mf = 0; mf < 4; mf++) {
            const int r = mbase + mf * 16 + gid;
            float2 v0 = make_float2(acc[mf][nf][0] + bv0, acc[mf][nf][1] + bv1);
            float2 v1 = make_float2(acc[mf][nf][2] + bv0, acc[mf][nf][3] + bv1);
            *(float2*)(C + (size_t)r * OUT_F + cc)       = v0;
            *(float2*)(C + (size_t)(r + 8) * OUT_F + cc) = v1;
        }
    }
}

// ---------------------------------------------------------------- launch
extern "C" void kernel_launch(void* const* d_in, const int* in_sizes, int n_in,
                              void* d_out, int out_size) {
    const float* x    = (const float*)d_in[0];   // [4,2048,4096]
    const float* cb   = (const float*)d_in[1];   // [4096,8]
    const void*  idx  = d_in[2];                 // [NBLOCKS] int32 or int64
    const float* bias = (const float*)d_in[3];   // [4096]
    float* out = (float*)d_out;

    k_init_flag<<<1, 1>>>();
    k_detect_idx32<<<(NBLOCKS / 2 + 255) / 256, 256>>>((const int*)idx);
    k_reconstruct<<<(NBLOCKS + 255) / 256, 256>>>(idx, cb);
    {
        size_t n8 = (size_t)MROWS * KDIM / 8;    // threads, 8 floats each
        k_to_half<<<(int)((n8 + 255) / 256), 256>>>((const float4*)x);
    }

    cudaFuncSetAttribute(k_gemm, cudaFuncAttributeMaxDynamicSharedMemorySize, SMEM_TOTAL);
    dim3 grid(OUT_F / BN, MROWS / BM);   // (16, 64)
    k_gemm<<<grid, 256, SMEM_TOTAL>>>(bias, out);
}

// round 5
// speedup vs baseline: 4.0467x; 1.0154x over previous
#include <cuda_runtime.h>
#include <cuda_fp16.h>
#include <cstdint>

// ---------------------------------------------------------------- constants
#define OUT_F   4096
#define IN_F    4096
#define KDIM    4096
#define MROWS   8192
#define NBLOCKS (OUT_F * IN_F / 8)        // 2,097,152

// GEMM tiling (fp16 mma.sync m16n8k16, cp.async pipeline)
#define BM      128
#define BN      256
#define BK      64                        // 64 fp16 = 128B row
#define NSTAGE  4
#define NITER   (KDIM / BK)               // 64
#define KSTEPS  (BK / 16)                 // 4 k16 steps per stage

#define A_STAGE_BYTES (BM * 128)          // 16 KB
#define B_STAGE_BYTES (BN * 128)          // 32 KB
#define STAGE_BYTES   (A_STAGE_BYTES + B_STAGE_BYTES)   // 48 KB
#define SMEM_TOTAL    (NSTAGE * STAGE_BYTES)            // 192 KB

// scratch: fp16(rn)-rounded operands
__device__ __half g_Wh[(size_t)OUT_F * IN_F];   // 34 MB
__device__ __half g_Xh[(size_t)MROWS * KDIM];   // 67 MB
__device__ int    g_idx_is32;

// ---------------------------------------------------------------- helpers
__device__ __forceinline__ uint32_t smem_u32(const void* p) {
    uint32_t a;
    asm("{ .reg .u64 t; cvta.to.shared.u64 t, %1; cvt.u32.u64 %0, t; }"
        : "=r"(a) : "l"(p));
    return a;
}

#define CP_ASYNC16(sm, gp) \
    asm volatile("cp.async.cg.shared.global [%0], [%1], 16;" :: "r"(sm), "l"(gp) : "memory")
#define CP_COMMIT() asm volatile("cp.async.commit_group;" ::: "memory")
#define CP_WAIT(n)  asm volatile("cp.async.wait_group %0;" :: "n"(n) : "memory")

#define LDMATRIX_X4(r, a) \
    asm volatile("ldmatrix.sync.aligned.m8n8.x4.shared.b16 {%0,%1,%2,%3}, [%4];" \
                 : "=r"((r)[0]), "=r"((r)[1]), "=r"((r)[2]), "=r"((r)[3]) : "r"(a))

__device__ __forceinline__ void mma_f16(float* c, const uint32_t* a, const uint32_t* b) {
    asm volatile(
        "mma.sync.aligned.m16n8k16.row.col.f32.f16.f16.f32 "
        "{%0,%1,%2,%3}, {%4,%5,%6,%7}, {%8,%9}, {%0,%1,%2,%3};"
        : "+f"(c[0]), "+f"(c[1]), "+f"(c[2]), "+f"(c[3])
        : "r"(a[0]), "r"(a[1]), "r"(a[2]), "r"(a[3]),
          "r"(b[0]), "r"(b[1]));
}

// ---------------------------------------------------------------- pre-passes
__global__ void k_init_flag() { g_idx_is32 = 0; }

__global__ void k_detect_idx32(const int* __restrict__ w) {
    int i = blockIdx.x * blockDim.x + threadIdx.x;
    int pos = 2 * i + 1;
    if (pos < NBLOCKS && w[pos] != 0) g_idx_is32 = 1;
}

__global__ void k_reconstruct(const void* __restrict__ indices,
                              const float* __restrict__ cb) {
    long long b = (long long)blockIdx.x * blockDim.x + threadIdx.x;
    if (b >= NBLOCKS) return;
    long long v;
    if (g_idx_is32) v = ((const int*)indices)[b];
    else            v = ((const long long*)indices)[b];
    const float4* src = (const float4*)(cb + v * 8);
    float4 lo = src[0], hi = src[1];
    __half2 h[4];
    h[0] = __floats2half2_rn(lo.x, lo.y);
    h[1] = __floats2half2_rn(lo.z, lo.w);
    h[2] = __floats2half2_rn(hi.x, hi.y);
    h[3] = __floats2half2_rn(hi.z, hi.w);
    *(uint4*)(g_Wh + b * 8) = *(uint4*)h;
}

__global__ void k_to_half(const float4* __restrict__ x) {
    size_t i = (size_t)blockIdx.x * blockDim.x + threadIdx.x;
    float4 a = x[2 * i], b = x[2 * i + 1];
    __half2 h[4];
    h[0] = __floats2half2_rn(a.x, a.y);
    h[1] = __floats2half2_rn(a.z, a.w);
    h[2] = __floats2half2_rn(b.x, b.y);
    h[3] = __floats2half2_rn(b.z, b.w);
    *(uint4*)(g_Xh + i * 8) = *(uint4*)h;
}

// ---------------------------------------------------------------- GEMM
// C[8192,4096] = X * W^T + bias. CTA 128x256, 8 warps (2M x 4N), warp 64x64.
// fp16 m16n8k16, ldmatrix.x4 (A rows / B pairs), k-step fragment double
// buffering, 4-stage cp.async, XOR-swizzled smem.
__global__ __launch_bounds__(256, 1)
void k_gemm(const float* __restrict__ bias, float* __restrict__ C) {
    extern __shared__ char smem[];
    const uint32_t smem_b = smem_u32(smem);

    const int tid  = threadIdx.x;
    const int lane = tid & 31;
    const int wid  = tid >> 5;
    const int gid  = lane >> 2;
    const int tg   = lane & 3;
    const int wm   = wid & 1;         // 0..1 (64 rows)
    const int wn   = wid >> 1;        // 0..3 (64 cols)

    const int m0 = blockIdx.y * BM;
    const int n0 = blockIdx.x * BN;

    // ---- cp.async addressing
    uint32_t sAoff[4], sBoff[8];
    const __half* gA[4];
    const __half* gB[8];
    #pragma unroll
    for (int i = 0; i < 4; i++) {
        int v = tid + i * 256, r = v >> 3, ch = v & 7;
        sAoff[i] = (uint32_t)(r * 128 + ((ch ^ (r & 7)) << 4));
        gA[i]    = g_Xh + (size_t)(m0 + r) * KDIM + ch * 8;
    }
    #pragma unroll
    for (int i = 0; i < 8; i++) {
        int v = tid + i * 256, r = v >> 3, ch = v & 7;
        sBoff[i] = (uint32_t)(r * 128 + ((ch ^ (r & 7)) << 4));
        gB[i]    = g_Wh + (size_t)(n0 + r) * KDIM + ch * 8;
    }

    // ---- ldmatrix per-lane bases (byte offsets within a stage)
    const int row_off = lane & 7;
    const int a_kb = lane >> 4;               // A k-half selector (x4: m2,m3)
    const int b_kb = (lane >> 3) & 1;         // B k-half selector (x4: m1,m3)
    uint32_t aoff[4], boff[4];
    #pragma unroll
    for (int mf = 0; mf < 4; mf++)
        aoff[mf] = (uint32_t)((wm * 64 + mf * 16 + row_off + ((lane >> 3) & 1) * 8) * 128);
    #pragma unroll
    for (int p = 0; p < 4; p++)               // B pair p -> nf = 2p, 2p+1
        boff[p] = (uint32_t)(A_STAGE_BYTES +
                  (wn * 64 + p * 16 + ((lane >> 4) & 1) * 8 + row_off) * 128);

    // ---- prefill
    #pragma unroll
    for (int s = 0; s < NSTAGE - 1; s++) {
        uint32_t ab = smem_b + s * STAGE_BYTES;
        uint32_t bb = ab + A_STAGE_BYTES;
        int kt = s * BK;
        #pragma unroll
        for (int i = 0; i < 4; i++) CP_ASYNC16(ab + sAoff[i], gA[i] + kt);
        #pragma unroll
        for (int i = 0; i < 8; i++) CP_ASYNC16(bb + sBoff[i], gB[i] + kt);
        CP_COMMIT();
    }

    float acc[4][8][4];
    #pragma unroll
    for (int mf = 0; mf < 4; mf++)
        #pragma unroll
        for (int nf = 0; nf < 8; nf++)
            #pragma unroll
            for (int r = 0; r < 4; r++) acc[mf][nf][r] = 0.f;

    // double-buffered fragments
    uint32_t a_frag[2][4][4];                 // [buf][mf][4]
    uint32_t b_frag[2][4][4];                 // [buf][pair][4] = b[2p][0],b[2p][1],b[2p+1][0],b[2p+1][1]

    for (int it = 0; it < NITER; it++) {
        const int s = it & (NSTAGE - 1);
        CP_WAIT(2);
        __syncthreads();

        const int nx = it + NSTAGE - 1;
        if (nx < NITER) {
            const int fs = nx & (NSTAGE - 1);
            uint32_t ab = smem_b + fs * STAGE_BYTES;
            uint32_t bb = ab + A_STAGE_BYTES;
            const int kt = nx * BK;
            #pragma unroll
            for (int j = 0; j < 4; j++) CP_ASYNC16(ab + sAoff[j], gA[j] + kt);
            #pragma unroll
            for (int j = 0; j < 8; j++) CP_ASYNC16(bb + sBoff[j], gB[j] + kt);
        }
        CP_COMMIT();

        const uint32_t stage = smem_b + s * STAGE_BYTES;

        // preload ks=0 fragments
        {
            const uint32_t ac = (uint32_t)((a_kb ^ row_off) << 4);
            const uint32_t bc = (uint32_t)((b_kb ^ row_off) << 4);
            #pragma unroll
            for (int mf = 0; mf < 4; mf++) LDMATRIX_X4(a_frag[0][mf], stage + aoff[mf] + ac);
            #pragma unroll
            for (int p = 0; p < 4; p++)    LDMATRIX_X4(b_frag[0][p],  stage + boff[p]  + bc);
        }

        #pragma unroll
        for (int ks = 0; ks < KSTEPS; ks++) {
            const int cur = ks & 1;
            if (ks + 1 < KSTEPS) {
                const int nb = cur ^ 1;
                const uint32_t ac = (uint32_t)((((2 * (ks + 1)) | a_kb) ^ row_off) << 4);
                const uint32_t bc = (uint32_t)((((2 * (ks + 1)) | b_kb) ^ row_off) << 4);
                #pragma unroll
                for (int mf = 0; mf < 4; mf++) LDMATRIX_X4(a_frag[nb][mf], stage + aoff[mf] + ac);
                #pragma unroll
                for (int p = 0; p < 4; p++)    LDMATRIX_X4(b_frag[nb][p],  stage + boff[p]  + bc);
            }
            #pragma unroll
            for (int mf = 0; mf < 4; mf++)
                #pragma unroll
                for (int p = 0; p < 4; p++) {
                    mma_f16(acc[mf][2 * p],     a_frag[cur][mf], &b_frag[cur][p][0]);
                    mma_f16(acc[mf][2 * p + 1], a_frag[cur][mf], &b_frag[cur][p][2]);
                }
        }
    }

    // ---- epilogue: bias + store
    const int mbase = m0 + wm * 64;
    const int nbase = n0 + wn * 64;
    #pragma unroll
    for (int nf = 0; nf < 8; nf++) {
        const int cc = nbase + nf * 8 + 2 * tg;
        const float bv0 = __ldg(bias + cc);
        const float bv1 = __ldg(bias + cc + 1);
        #pragma unroll
        for (int mf = 0; mf < 4; mf++) {
            const int r = mbase + mf * 16 + gid;
            float2 v0 = make_float2(acc[mf][nf][0] + bv0, acc[mf][nf][1] + bv1);
            float2 v1 = make_float2(acc[mf][nf][2] + bv0, acc[mf][nf][3] + bv1);
            *(float2*)(C + (size_t)r * OUT_F + cc)       = v0;
            *(float2*)(C + (size_t)(r + 8) * OUT_F + cc) = v1;
        }
    }
}

// ---------------------------------------------------------------- launch
extern "C" void kernel_launch(void* const* d_in, const int* in_sizes, int n_in,
                              void* d_out, int out_size) {
    const float* x    = (const float*)d_in[0];   // [4,2048,4096]
    const float* cb   = (const float*)d_in[1];   // [4096,8]
    const void*  idx  = d_in[2];                 // [NBLOCKS] int32 or int64
    const float* bias = (const float*)d_in[3];   // [4096]
    float* out = (float*)d_out;

    k_init_flag<<<1, 1>>>();
    k_detect_idx32<<<(NBLOCKS / 2 + 255) / 256, 256>>>((const int*)idx);
    k_reconstruct<<<(NBLOCKS + 255) / 256, 256>>>(idx, cb);
    {
        size_t n8 = (size_t)MROWS * KDIM / 8;
        k_to_half<<<(int)((n8 + 255) / 256), 256>>>((const float4*)x);
    }

    cudaFuncSetAttribute(k_gemm, cudaFuncAttributeMaxDynamicSharedMemorySize, SMEM_TOTAL);
    dim3 grid(OUT_F / BN, MROWS / BM);   // (16, 64)
    k_gemm<<<grid, 256, SMEM_TOTAL>>>(bias, out);
}

// round 6
// speedup vs baseline: 4.2503x; 1.0503x over previous
#include <cuda_runtime.h>
#include <cuda_fp16.h>
#include <cstdint>

// ---------------------------------------------------------------- constants
#define OUT_F   4096
#define IN_F    4096
#define KDIM    4096
#define MROWS   8192
#define NBLOCKS (OUT_F * IN_F / 8)        // 2,097,152

// GEMM tiling (fp16 mma.sync m16n8k16, 2-stage x BK=128 cp.async ring)
#define BM      128
#define BN      256
#define BK      128                       // two 64-wide k-halves per stage
#define NSTAGE  2
#define NITER   (KDIM / BK)               // 32
#define KSTEPS  (BK / 16)                 // 8 k16 steps per stage

// stage = [A0 16K][A1 16K][B0 32K][B1 32K] = 96 KB (each half: 128B rows)
#define A_HALF_BYTES  (BM * 128)          // 16 KB
#define B_HALF_BYTES  (BN * 128)          // 32 KB
#define B_BASE_OFF    (2 * A_HALF_BYTES)  // 32 KB
#define STAGE_BYTES   (2 * A_HALF_BYTES + 2 * B_HALF_BYTES)   // 96 KB
#define SMEM_TOTAL    (NSTAGE * STAGE_BYTES)                  // 192 KB

// scratch: fp16(rn)-rounded operands
__device__ __half g_Wh[(size_t)OUT_F * IN_F];   // 34 MB
__device__ __half g_Xh[(size_t)MROWS * KDIM];   // 67 MB
__device__ int    g_idx_is32 = 0;               // zero-init at load; replay-stable

// ---------------------------------------------------------------- helpers
__device__ __forceinline__ uint32_t smem_u32(const void* p) {
    uint32_t a;
    asm("{ .reg .u64 t; cvta.to.shared.u64 t, %1; cvt.u32.u64 %0, t; }"
        : "=r"(a) : "l"(p));
    return a;
}

#define CP_ASYNC16(sm, gp) \
    asm volatile("cp.async.cg.shared.global [%0], [%1], 16;" :: "r"(sm), "l"(gp) : "memory")
#define CP_COMMIT() asm volatile("cp.async.commit_group;" ::: "memory")
#define CP_WAIT(n)  asm volatile("cp.async.wait_group %0;" :: "n"(n) : "memory")

#define LDMATRIX_X4(r, a) \
    asm volatile("ldmatrix.sync.aligned.m8n8.x4.shared.b16 {%0,%1,%2,%3}, [%4];" \
                 : "=r"((r)[0]), "=r"((r)[1]), "=r"((r)[2]), "=r"((r)[3]) : "r"(a))

__device__ __forceinline__ void mma_f16(float* c, const uint32_t* a, const uint32_t* b) {
    asm volatile(
        "mma.sync.aligned.m16n8k16.row.col.f32.f16.f16.f32 "
        "{%0,%1,%2,%3}, {%4,%5,%6,%7}, {%8,%9}, {%0,%1,%2,%3};"
        : "+f"(c[0]), "+f"(c[1]), "+f"(c[2]), "+f"(c[3])
        : "r"(a[0]), "r"(a[1]), "r"(a[2]), "r"(a[3]),
          "r"(b[0]), "r"(b[1]));
}

// ---------------------------------------------------------------- pre-passes
__global__ void k_detect_idx32(const int* __restrict__ w) {
    int i = blockIdx.x * blockDim.x + threadIdx.x;
    int pos = 2 * i + 1;
    if (pos < NBLOCKS && w[pos] != 0) g_idx_is32 = 1;
}

__global__ void k_reconstruct(const void* __restrict__ indices,
                              const float* __restrict__ cb) {
    long long b = (long long)blockIdx.x * blockDim.x + threadIdx.x;
    if (b >= NBLOCKS) return;
    long long v;
    if (g_idx_is32) v = ((const int*)indices)[b];
    else            v = ((const long long*)indices)[b];
    const float4* src = (const float4*)(cb + v * 8);
    float4 lo = src[0], hi = src[1];
    __half2 h[4];
    h[0] = __floats2half2_rn(lo.x, lo.y);
    h[1] = __floats2half2_rn(lo.z, lo.w);
    h[2] = __floats2half2_rn(hi.x, hi.y);
    h[3] = __floats2half2_rn(hi.z, hi.w);
    *(uint4*)(g_Wh + b * 8) = *(uint4*)h;
}

__global__ void k_to_half(const float4* __restrict__ x) {
    size_t i = (size_t)blockIdx.x * blockDim.x + threadIdx.x;
    float4 a = x[2 * i], b = x[2 * i + 1];
    __half2 h[4];
    h[0] = __floats2half2_rn(a.x, a.y);
    h[1] = __floats2half2_rn(a.z, a.w);
    h[2] = __floats2half2_rn(b.x, b.y);
    h[3] = __floats2half2_rn(b.z, b.w);
    *(uint4*)(g_Xh + i * 8) = *(uint4*)h;
}

// ---------------------------------------------------------------- GEMM
__global__ __launch_bounds__(256, 1)
void k_gemm(const float* __restrict__ bias, float* __restrict__ C) {
    extern __shared__ char smem[];
    const uint32_t smem_b = smem_u32(smem);

    const int tid  = threadIdx.x;
    const int lane = tid & 31;
    const int wid  = tid >> 5;
    const int gid  = lane >> 2;
    const int tg   = lane & 3;
    const int wm   = wid & 1;         // 0..1 (64 rows)
    const int wn   = wid >> 1;        // 0..3 (64 cols)

    const int m0 = blockIdx.y * BM;
    const int n0 = blockIdx.x * BN;

    // ---- cp.async addressing (per 64-wide k-half; rows step by 32 => swizzle
    //      term (r&7) is i-invariant)
    uint32_t sAoff[4], sBoff[8];
    const __half* gA[4];
    const __half* gB[8];
    #pragma unroll
    for (int i = 0; i < 4; i++) {
        int v = tid + i * 256, r = v >> 3, ch = v & 7;
        sAoff[i] = (uint32_t)(r * 128 + ((ch ^ (r & 7)) << 4));
        gA[i]    = g_Xh + (size_t)(m0 + r) * KDIM + ch * 8;
    }
    #pragma unroll
    for (int i = 0; i < 8; i++) {
        int v = tid + i * 256, r = v >> 3, ch = v & 7;
        sBoff[i] = (uint32_t)(r * 128 + ((ch ^ (r & 7)) << 4));
        gB[i]    = g_Wh + (size_t)(n0 + r) * KDIM + ch * 8;
    }

    // ---- ldmatrix per-lane bases (within a 64-wide half-block)
    const int row_off = lane & 7;
    const int a_kb = lane >> 4;
    const int b_kb = (lane >> 3) & 1;
    uint32_t aoff[4], boff[4];
    #pragma unroll
    for (int mf = 0; mf < 4; mf++)
        aoff[mf] = (uint32_t)((wm * 64 + mf * 16 + row_off + ((lane >> 3) & 1) * 8) * 128);
    #pragma unroll
    for (int p = 0; p < 4; p++)
        boff[p] = (uint32_t)((wn * 64 + p * 16 + ((lane >> 4) & 1) * 8 + row_off) * 128);

    // ---- fill one 96KB stage with k-tile starting at kt (two 64-halves)
    auto fill_stage = [&](uint32_t sb, int kt) {
        #pragma unroll
        for (int kh = 0; kh < 2; kh++) {
            uint32_t ab = sb + kh * A_HALF_BYTES;
            uint32_t bb = sb + B_BASE_OFF + kh * B_HALF_BYTES;
            const int ko = kt + kh * 64;
            #pragma unroll
            for (int i = 0; i < 4; i++) CP_ASYNC16(ab + sAoff[i], gA[i] + ko);
            #pragma unroll
            for (int i = 0; i < 8; i++) CP_ASYNC16(bb + sBoff[i], gB[i] + ko);
        }
    };

    // prefill stage 0
    fill_stage(smem_b, 0);
    CP_COMMIT();

    float acc[4][8][4];
    #pragma unroll
    for (int mf = 0; mf < 4; mf++)
        #pragma unroll
        for (int nf = 0; nf < 8; nf++)
            #pragma unroll
            for (int r = 0; r < 4; r++) acc[mf][nf][r] = 0.f;

    uint32_t a_frag[2][4][4];
    uint32_t b_frag[2][4][4];

    for (int it = 0; it < NITER; it++) {
        const int s = it & 1;
        const uint32_t stage = smem_b + s * STAGE_BYTES;

        CP_WAIT(0);           // only outstanding group = fill(it)
        __syncthreads();      // all threads: fill visible AND done computing s^1

        if (it + 1 < NITER) {
            fill_stage(smem_b + (s ^ 1) * STAGE_BYTES, (it + 1) * BK);
            CP_COMMIT();
        }

        // preload ks=0 fragments
        {
            const uint32_t ac = (uint32_t)((a_kb ^ row_off) << 4);
            const uint32_t bc = (uint32_t)((b_kb ^ row_off) << 4);
            #pragma unroll
            for (int mf = 0; mf < 4; mf++) LDMATRIX_X4(a_frag[0][mf], stage + aoff[mf] + ac);
            #pragma unroll
            for (int p = 0; p < 4; p++)
                LDMATRIX_X4(b_frag[0][p], stage + B_BASE_OFF + boff[p] + bc);
        }

        #pragma unroll
        for (int ks = 0; ks < KSTEPS; ks++) {
            const int cur = ks & 1;
            if (ks + 1 < KSTEPS) {
                const int nb  = cur ^ 1;
                const int kn  = ks + 1;
                const int kh  = kn >> 2;          // which 64-half
                const int kk  = kn & 3;           // k16 step within half
                const uint32_t abase = stage + kh * A_HALF_BYTES;
                const uint32_t bbase = stage + B_BASE_OFF + kh * B_HALF_BYTES;
                const uint32_t ac = (uint32_t)((((2 * kk) | a_kb) ^ row_off) << 4);
                const uint32_t bc = (uint32_t)((((2 * kk) | b_kb) ^ row_off) << 4);
                #pragma unroll
                for (int mf = 0; mf < 4; mf++) LDMATRIX_X4(a_frag[nb][mf], abase + aoff[mf] + ac);
                #pragma unroll
                for (int p = 0; p < 4; p++)    LDMATRIX_X4(b_frag[nb][p],  bbase + boff[p]  + bc);
            }
            #pragma unroll
            for (int mf = 0; mf < 4; mf++)
                #pragma unroll
                for (int p = 0; p < 4; p++) {
                    mma_f16(acc[mf][2 * p],     a_frag[cur][mf], &b_frag[cur][p][0]);
                    mma_f16(acc[mf][2 * p + 1], a_frag[cur][mf], &b_frag[cur][p][2]);
                }
        }
    }

    // ---- epilogue: bias + store
    const int mbase = m0 + wm * 64;
    const int nbase = n0 + wn * 64;
    #pragma unroll
    for (int nf = 0; nf < 8; nf++) {
        const int cc = nbase + nf * 8 + 2 * tg;
        const float bv0 = __ldg(bias + cc);
        const float bv1 = __ldg(bias + cc + 1);
        #pragma unroll
        for (int mf = 0; mf < 4; mf++) {
            const int r = mbase + mf * 16 + gid;
            float2 v0 = make_float2(acc[mf][nf][0] + bv0, acc[mf][nf][1] + bv1);
            float2 v1 = make_float2(acc[mf][nf][2] + bv0, acc[mf][nf][3] + bv1);
            *(float2*)(C + (size_t)r * OUT_F + cc)       = v0;
            *(float2*)(C + (size_t)(r + 8) * OUT_F + cc) = v1;
        }
    }
}

// ---------------------------------------------------------------- launch
extern "C" void kernel_launch(void* const* d_in, const int* in_sizes, int n_in,
                              void* d_out, int out_size) {
    const float* x    = (const float*)d_in[0];   // [4,2048,4096]
    const float* cb   = (const float*)d_in[1];   // [4096,8]
    const void*  idx  = d_in[2];                 // [NBLOCKS] int32 or int64
    const float* bias = (const float*)d_in[3];   // [4096]
    float* out = (float*)d_out;

    k_detect_idx32<<<(NBLOCKS / 2 + 255) / 256, 256>>>((const int*)idx);
    k_reconstruct<<<(NBLOCKS + 255) / 256, 256>>>(idx, cb);
    {
        size_t n8 = (size_t)MROWS * KDIM / 8;
        k_to_half<<<(int)((n8 + 255) / 256), 256>>>((const float4*)x);
    }

    cudaFuncSetAttribute(k_gemm, cudaFuncAttributeMaxDynamicSharedMemorySize, SMEM_TOTAL);
    dim3 grid(OUT_F / BN, MROWS / BM);   // (16, 64)
    k_gemm<<<grid, 256, SMEM_TOTAL>>>(bias, out);
}

// round 8
// speedup vs baseline: 4.4974x; 1.0581x over previous
#include <cuda_runtime.h>
#include <cuda_fp16.h>
#include <cstdint>

// ---------------------------------------------------------------- constants
#define OUT_F   4096
#define IN_F    4096
#define KDIM    4096
#define MROWS   8192
#define NBLOCKS (OUT_F * IN_F / 8)        // 2,097,152

// GEMM tiling (fp16 mma.sync m16n8k16, 2-stage x BK=128 cp.async ring)
#define BM      128
#define BN      256
#define BK      128
#define NITER   (KDIM / BK)               // 32
#define KSTEPS  (BK / 16)                 // 8

#define A_HALF_BYTES  (BM * 128)          // 16 KB
#define B_HALF_BYTES  (BN * 128)          // 32 KB
#define B_BASE_OFF    (2 * A_HALF_BYTES)  // 32 KB
#define STAGE_BYTES   (2 * A_HALF_BYTES + 2 * B_HALF_BYTES)   // 96 KB
#define SMEM_TOTAL    (2 * STAGE_BYTES)                       // 192 KB

__device__ __half g_Wh[(size_t)OUT_F * IN_F];   // 34 MB
__device__ __half g_Xh[(size_t)MROWS * KDIM];   // 67 MB

// ---------------------------------------------------------------- helpers
__device__ __forceinline__ uint32_t smem_u32(const void* p) {
    uint32_t a;
    asm("{ .reg .u64 t; cvta.to.shared.u64 t, %1; cvt.u32.u64 %0, t; }"
        : "=r"(a) : "l"(p));
    return a;
}

#define CP_ASYNC16(sm, gp) \
    asm volatile("cp.async.cg.shared.global [%0], [%1], 16;" :: "r"(sm), "l"(gp) : "memory")
#define CP_COMMIT() asm volatile("cp.async.commit_group;" ::: "memory")
#define CP_WAIT(n)  asm volatile("cp.async.wait_group %0;" :: "n"(n) : "memory")

#define LDMATRIX_X4(r, a) \
    asm volatile("ldmatrix.sync.aligned.m8n8.x4.shared.b16 {%0,%1,%2,%3}, [%4];" \
                 : "=r"((r)[0]), "=r"((r)[1]), "=r"((r)[2]), "=r"((r)[3]) : "r"(a))

__device__ __forceinline__ void mma_f16(float* c, const uint32_t* a, const uint32_t* b) {
    asm volatile(
        "mma.sync.aligned.m16n8k16.row.col.f32.f16.f16.f32 "
        "{%0,%1,%2,%3}, {%4,%5,%6,%7}, {%8,%9}, {%0,%1,%2,%3};"
        : "+f"(c[0]), "+f"(c[1]), "+f"(c[2]), "+f"(c[3])
        : "r"(a[0]), "r"(a[1]), "r"(a[2]), "r"(a[3]),
          "r"(b[0]), "r"(b[1]));
}

// ---------------------------------------------------------------- pre-passes
// Reconstruct W (fp16 rn) with fused block-local index-dtype detection.
// Sniff: sample 32 odd word-indices in [B0, NBLOCKS) — if the buffer is int64
// (LE), odd words are hi-halves of values < 4096 => all zero. If int32 they
// are random indices; P(all 32 == 0) = 4096^-32 ~ 0. Deterministic per input.
__global__ void k_reconstruct(const void* __restrict__ indices,
                              const float* __restrict__ cb) {
    __shared__ int s_is32;
    const long long B0 = (long long)blockIdx.x * blockDim.x;   // first block idx
    if (threadIdx.x == 0) s_is32 = 0;
    __syncthreads();
    if (threadIdx.x < 32) {
        long long w = (B0 + 2 * threadIdx.x) | 1;              // odd, < NBLOCKS
        if (w < NBLOCKS && ((const int*)indices)[w] != 0) s_is32 = 1;
    }
    __syncthreads();

    long long b = B0 + threadIdx.x;
    if (b >= NBLOCKS) return;
    long long v;
    if (s_is32) v = ((const int*)indices)[b];
    else        v = ((const long long*)indices)[b];
    const float4* src = (const float4*)(cb + v * 8);
    float4 lo = src[0], hi = src[1];
    __half2 h[4];
    h[0] = __floats2half2_rn(lo.x, lo.y);
    h[1] = __floats2half2_rn(lo.z, lo.w);
    h[2] = __floats2half2_rn(hi.x, hi.y);
    h[3] = __floats2half2_rn(hi.z, hi.w);
    *(uint4*)(g_Wh + b * 8) = *(uint4*)h;
}

__global__ void k_to_half(const float4* __restrict__ x) {
    size_t i = (size_t)blockIdx.x * blockDim.x + threadIdx.x;
    float4 a = x[2 * i], b = x[2 * i + 1];
    __half2 h[4];
    h[0] = __floats2half2_rn(a.x, a.y);
    h[1] = __floats2half2_rn(a.z, a.w);
    h[2] = __floats2half2_rn(b.x, b.y);
    h[3] = __floats2half2_rn(b.z, b.w);
    *(uint4*)(g_Xh + i * 8) = *(uint4*)h;
}

// ---------------------------------------------------------------- GEMM
__global__ __launch_bounds__(256, 1)
void k_gemm(const float* __restrict__ bias, float* __restrict__ C) {
    extern __shared__ char smem[];
    const uint32_t smem_b = smem_u32(smem);

    const int tid  = threadIdx.x;
    const int lane = tid & 31;
    const int wid  = tid >> 5;
    const int gid  = lane >> 2;
    const int tg   = lane & 3;
    const int wm   = wid & 1;
    const int wn   = wid >> 1;

    const int m0 = blockIdx.y * BM;
    const int n0 = blockIdx.x * BN;

    // ---- fill op table: 24 x 16B cp.async per thread per stage
    // o in [0,8): A half=o>>2, slot=o&3 ; o in [8,24): B half=(o-8)>>3, slot=(o-8)&7
    uint32_t sOff[24];          // smem offset within stage
    const __half* gPtr[24];     // global base (add k offset)
    #pragma unroll
    for (int i = 0; i < 4; i++) {
        int v = tid + i * 256, r = v >> 3, ch = v & 7;
        uint32_t so = (uint32_t)(r * 128 + ((ch ^ (r & 7)) << 4));
        const __half* gp = g_Xh + (size_t)(m0 + r) * KDIM + ch * 8;
        #pragma unroll
        for (int kh = 0; kh < 2; kh++) {
            sOff[kh * 4 + i] = kh * A_HALF_BYTES + so;
            gPtr[kh * 4 + i] = gp + kh * 64;
        }
    }
    #pragma unroll
    for (int i = 0; i < 8; i++) {
        int v = tid + i * 256, r = v >> 3, ch = v & 7;
        uint32_t so = (uint32_t)(B_BASE_OFF + r * 128 + ((ch ^ (r & 7)) << 4));
        const __half* gp = g_Wh + (size_t)(n0 + r) * KDIM + ch * 8;
        #pragma unroll
        for (int kh = 0; kh < 2; kh++) {
            sOff[8 + kh * 8 + i] = kh * B_HALF_BYTES + so;
            gPtr[8 + kh * 8 + i] = gp + kh * 64;
        }
    }

    // ---- ldmatrix per-lane bases
    const int row_off = lane & 7;
    const int a_kb = lane >> 4;
    const int b_kb = (lane >> 3) & 1;
    uint32_t aoff[4], boff[4];
    #pragma unroll
    for (int mf = 0; mf < 4; mf++)
        aoff[mf] = (uint32_t)((wm * 64 + mf * 16 + row_off + ((lane >> 3) & 1) * 8) * 128);
    #pragma unroll
    for (int p = 0; p < 4; p++)
        boff[p] = (uint32_t)((wn * 64 + p * 16 + ((lane >> 4) & 1) * 8 + row_off) * 128);

    // ---- prefill stage 0 (burst; nothing to overlap yet)
    #pragma unroll
    for (int o = 0; o < 24; o++) CP_ASYNC16(smem_b + sOff[o], gPtr[o]);
    CP_COMMIT();

    float acc[4][8][4];
    #pragma unroll
    for (int mf = 0; mf < 4; mf++)
        #pragma unroll
        for (int nf = 0; nf < 8; nf++)
            #pragma unroll
            for (int r = 0; r < 4; r++) acc[mf][nf][r] = 0.f;

    uint32_t a_frag[2][4][4];
    uint32_t b_frag[2][4][4];

    for (int it = 0; it < NITER; it++) {
        const int s = it & 1;
        const uint32_t stage = smem_b + s * STAGE_BYTES;
        const uint32_t nstage = smem_b + (s ^ 1) * STAGE_BYTES;
        const int knext = (it + 1) * BK;
        const bool do_fill = (it + 1 < NITER);

        CP_WAIT(0);
        __syncthreads();

        // preload ks=0 fragments
        {
            const uint32_t ac = (uint32_t)((a_kb ^ row_off) << 4);
            const uint32_t bc = (uint32_t)((b_kb ^ row_off) << 4);
            #pragma unroll
            for (int mf = 0; mf < 4; mf++) LDMATRIX_X4(a_frag[0][mf], stage + aoff[mf] + ac);
            #pragma unroll
            for (int p = 0; p < 4; p++)
                LDMATRIX_X4(b_frag[0][p], stage + B_BASE_OFF + boff[p] + bc);
        }

        #pragma unroll
        for (int ks = 0; ks < KSTEPS; ks++) {
            const int cur = ks & 1;
            // spread next-stage fill: 3 cp.async per k-step
            if (do_fill) {
                #pragma unroll
                for (int j = 0; j < 3; j++) {
                    const int o = ks * 3 + j;
                    CP_ASYNC16(nstage + sOff[o], gPtr[o] + knext);
                }
            }
            if (ks + 1 < KSTEPS) {
                const int nb  = cur ^ 1;
                const int kn  = ks + 1;
                const int kh  = kn >> 2;
                const int kk  = kn & 3;
                const uint32_t abase = stage + kh * A_HALF_BYTES;
                const uint32_t bbase = stage + B_BASE_OFF + kh * B_HALF_BYTES;
                const uint32_t ac = (uint32_t)((((2 * kk) | a_kb) ^ row_off) << 4);
                const uint32_t bc = (uint32_t)((((2 * kk) | b_kb) ^ row_off) << 4);
                #pragma unroll
                for (int mf = 0; mf < 4; mf++) LDMATRIX_X4(a_frag[nb][mf], abase + aoff[mf] + ac);
                #pragma unroll
                for (int p = 0; p < 4; p++)    LDMATRIX_X4(b_frag[nb][p],  bbase + boff[p]  + bc);
            }
            #pragma unroll
            for (int mf = 0; mf < 4; mf++)
                #pragma unroll
                for (int p = 0; p < 4; p++) {
                    mma_f16(acc[mf][2 * p],     a_frag[cur][mf], &b_frag[cur][p][0]);
                    mma_f16(acc[mf][2 * p + 1], a_frag[cur][mf], &b_frag[cur][p][2]);
                }
        }
        CP_COMMIT();
    }

    // ---- epilogue: bias + store
    const int mbase = m0 + wm * 64;
    const int nbase = n0 + wn * 64;
    #pragma unroll
    for (int nf = 0; nf < 8; nf++) {
        const int cc = nbase + nf * 8 + 2 * tg;
        const float bv0 = __ldg(bias + cc);
        const float bv1 = __ldg(bias + cc + 1);
        #pragma unroll
        for (int mf = 0; mf < 4; mf++) {
            const int r = mbase + mf * 16 + gid;
            float2 v0 = make_float2(acc[mf][nf][0] + bv0, acc[mf][nf][1] + bv1);
            float2 v1 = make_float2(acc[mf][nf][2] + bv0, acc[mf][nf][3] + bv1);
            *(float2*)(C + (size_t)r * OUT_F + cc)       = v0;
            *(float2*)(C + (size_t)(r + 8) * OUT_F + cc) = v1;
        }
    }
}

// ---------------------------------------------------------------- launch
extern "C" void kernel_launch(void* const* d_in, const int* in_sizes, int n_in,
                              void* d_out, int out_size) {
    const float* x    = (const float*)d_in[0];   // [4,2048,4096]
    const float* cb   = (const float*)d_in[1];   // [4096,8]
    const void*  idx  = d_in[2];                 // [NBLOCKS] int32 or int64
    const float* bias = (const float*)d_in[3];   // [4096]
    float* out = (float*)d_out;

    {
        size_t n8 = (size_t)MROWS * KDIM / 8;
        k_to_half<<<(int)((n8 + 255) / 256), 256>>>((const float4*)x);
    }
    k_reconstruct<<<(NBLOCKS + 255) / 256, 256>>>(idx, cb);

    cudaFuncSetAttribute(k_gemm, cudaFuncAttributeMaxDynamicSharedMemorySize, SMEM_TOTAL);
    dim3 grid(OUT_F / BN, MROWS / BM);   // (16, 64)
    k_gemm<<<grid, 256, SMEM_TOTAL>>>(bias, out);
}